// round 4
// baseline (speedup 1.0000x reference)
#include <cuda_runtime.h>
#include <cuda_fp16.h>
#include <cstdint>

#define BB 8
#define CC 64
#define NN 4096
#define KK 20
#define KH 24          /* heap size per column-half */
#define NCAND 48
#define OUTC 64
#define TM 128
#define TN 128

// ===================== device scratch (allocation-free) =====================
__device__ __half g_hi[(size_t)BB * NN * CC];
__device__ float g_xp[(size_t)BB * NN * CC];     // point-major fp32 copy
__device__ float g_sq[BB * NN];
__device__ int   g_cand[(size_t)BB * NN * NCAND];
__device__ int   g_idx[BB * NN * KK];
__device__ float g_u[(size_t)BB * NN * OUTC];
__device__ float g_v[(size_t)BB * NN * OUTC];
__device__ float g_mx[(size_t)BB * NN * OUTC];
__device__ float g_mn[(size_t)BB * NN * OUTC];
__device__ float g_sum[OUTC];
__device__ float g_sumsq[OUTC];
__device__ float g_s[OUTC];
__device__ float g_t[OUTC];

// ===================== mma / ldmatrix helpers =====================
__device__ __forceinline__ void ldsm_x4(uint32_t addr, uint32_t* r) {
    asm volatile("ldmatrix.sync.aligned.m8n8.x4.shared.b16 {%0,%1,%2,%3}, [%4];"
                 : "=r"(r[0]), "=r"(r[1]), "=r"(r[2]), "=r"(r[3]) : "r"(addr));
}
__device__ __forceinline__ void mma16816(float* d, const uint32_t* a, const uint32_t* b) {
    asm volatile("mma.sync.aligned.m16n8k16.row.col.f32.f16.f16.f32 "
                 "{%0,%1,%2,%3}, {%4,%5,%6,%7}, {%8,%9}, {%0,%1,%2,%3};"
                 : "+f"(d[0]), "+f"(d[1]), "+f"(d[2]), "+f"(d[3])
                 : "r"(a[0]), "r"(a[1]), "r"(a[2]), "r"(a[3]), "r"(b[0]), "r"(b[1]));
}
__device__ __forceinline__ uint32_t smem_u32(const void* p) {
    uint32_t a;
    asm("{ .reg .u64 t; cvta.to.shared.u64 t, %1; cvt.u32.u64 %0, t; }" : "=r"(a) : "l"(p));
    return a;
}

// ===================== kernel A: sq norms + fp16 hi + fp32 point-major =====================
__global__ void __launch_bounds__(128) prep_kernel(const float* __restrict__ x) {
    int p = blockIdx.x * 128 + threadIdx.x;
    int b = p >> 12;
    int n = p & (NN - 1);
    const float* xb = x + (size_t)b * CC * NN + n;
    float s = 0.f;
#pragma unroll
    for (int g = 0; g < 8; g++) {
        uint4 h4;
        unsigned short* hp = (unsigned short*)&h4;
        float vf[8];
#pragma unroll
        for (int e = 0; e < 8; e++) {
            float v = xb[(size_t)(g * 8 + e) * NN];
            vf[e] = v;
            s = fmaf(v, v, s);
            hp[e] = __half_as_ushort(__float2half_rn(v));
        }
        *reinterpret_cast<uint4*>(g_hi + (size_t)p * CC + g * 8) = h4;
        *reinterpret_cast<float4*>(g_xp + (size_t)p * CC + g * 8) =
            make_float4(vf[0], vf[1], vf[2], vf[3]);
        *reinterpret_cast<float4*>(g_xp + (size_t)p * CC + g * 8 + 4) =
            make_float4(vf[4], vf[5], vf[6], vf[7]);
    }
    g_sq[p] = s;
    if (blockIdx.x == 0 && threadIdx.x < OUTC) {
        g_sum[threadIdx.x] = 0.f;
        g_sumsq[threadIdx.x] = 0.f;
    }
}

// ===================== kernel B: 1-pass mma.sync GEMM + fused top-24/half =====================
#define SM_A     0          /* 128*144 = 18432 */
#define SM_B     18432      /* 2 * 18432 */
#define SM_DST   55296      /* 128*130*4 = 66560 */
#define SM_SQS   121856     /* 2*128*4 = 1024 */
#define SM_HD    122880     /* 24*256*4 = 24576 */
#define SM_HIX   147456     /* 24576 */
#define SM_TOTAL 172032

__device__ __forceinline__ void heap_insert(float sc, int c, float* hD, int* hI, int tid) {
    int node = 0;
    while (true) {
        int l = 2 * node + 1, r = 2 * node + 2;
        int big = node;
        float bd = sc;
        if (l < KH) { float ld = hD[l * 256 + tid]; if (ld > bd) { bd = ld; big = l; } }
        if (r < KH) { float rd = hD[r * 256 + tid]; if (rd > bd) { bd = rd; big = r; } }
        if (big == node) break;
        hD[node * 256 + tid] = hD[big * 256 + tid];
        hI[node * 256 + tid] = hI[big * 256 + tid];
        node = big;
    }
    hD[node * 256 + tid] = sc;
    hI[node * 256 + tid] = c;
}

__global__ void __launch_bounds__(256, 1) knn_mma_kernel() {
    extern __shared__ char sm[];
    const uint32_t smb = smem_u32(sm);
    const int tid = threadIdx.x;
    const int wid = tid >> 5;
    const int lane = tid & 31;
    const int b = blockIdx.y;
    const int row0 = blockIdx.x * TM;

    const __half* hi_b = g_hi + (size_t)b * NN * CC;
    float* Dst = (float*)(sm + SM_DST);
    float* sqs = (float*)(sm + SM_SQS);
    float* hD  = (float*)(sm + SM_HD);
    int*   hI  = (int*)(sm + SM_HIX);

    // ---- load A rows, padded stride 144B ----
    for (int t = 0; t < 4; t++) {
        int i = tid + t * 256;
        int m = i >> 3, j = i & 7;
        *reinterpret_cast<uint4*>(sm + SM_A + m * 144 + j * 16) =
            *reinterpret_cast<const uint4*>(hi_b + (size_t)(row0 + m) * CC + j * 8);
    }
#pragma unroll
    for (int j = 0; j < KH; j++) { hD[j * 256 + tid] = 3.0e38f; hI[j * 256 + tid] = 0; }
    float rootD = 3.0e38f;

    // ---- B tile 0 ----
    for (int t = 0; t < 4; t++) {
        int i = tid + t * 256;
        int n = i >> 3, j = i & 7;
        *reinterpret_cast<uint4*>(sm + SM_B + n * 144 + j * 16) =
            *reinterpret_cast<const uint4*>(hi_b + (size_t)n * CC + j * 8);
    }
    if (tid < 128) sqs[tid] = g_sq[b * NN + tid];
    __syncthreads();

    const int m0 = wid * 16;
    const int erow = tid & 127;
    const int ech = tid >> 7;           // which 64-col half of the 128-col tile

    uint4 pre[4];

    for (int ct = 0; ct < NN / TN; ct++) {
        int buf = ct & 1;
        uint32_t bsm = smb + SM_B + (uint32_t)buf * 18432u;

        // prefetch next B tile to registers (overlaps MMA)
        if (ct + 1 < NN / TN) {
            int col0 = (ct + 1) * TN;
#pragma unroll
            for (int t = 0; t < 4; t++) {
                int i = tid + t * 256;
                int n = i >> 3, j = i & 7;
                pre[t] = *reinterpret_cast<const uint4*>(hi_b + (size_t)(col0 + n) * CC + j * 8);
            }
        }

        // ---- MMA: D[128x128] = A(128x64) . B^T(64x128), single hi pass ----
        float acc[16][4];
#pragma unroll
        for (int nt = 0; nt < 16; nt++)
#pragma unroll
            for (int e = 0; e < 4; e++) acc[nt][e] = 0.f;

#pragma unroll
        for (int ks = 0; ks < 4; ks++) {
            uint32_t ah[4];
            uint32_t aoff = (uint32_t)(m0 + (lane & 15)) * 144u +
                            (uint32_t)(ks * 16 + ((lane >> 4) << 3)) * 2u;
            ldsm_x4(smb + SM_A + aoff, ah);
#pragma unroll
            for (int ntp = 0; ntp < 8; ntp++) {
                uint32_t bh[4];
                uint32_t bn = (uint32_t)(ntp * 16 + ((lane >> 4) << 3) + (lane & 7));
                uint32_t bk = (uint32_t)(ks * 16 + (((lane >> 3) & 1) << 3));
                ldsm_x4(bsm + bn * 144u + bk * 2u, bh);
                mma16816(acc[2 * ntp],     ah, bh);
                mma16816(acc[2 * ntp + 1], ah, bh + 2);
            }
        }

        __syncthreads();   // B smem free; prev epilogue done with Dst

        // store next B tile
        if (ct + 1 < NN / TN) {
            char* dstb = sm + SM_B + (buf ^ 1) * 18432;
#pragma unroll
            for (int t = 0; t < 4; t++) {
                int i = tid + t * 256;
                int n = i >> 3, j = i & 7;
                *reinterpret_cast<uint4*>(dstb + n * 144 + j * 16) = pre[t];
            }
            if (tid < 128) sqs[(buf ^ 1) * 128 + tid] = g_sq[b * NN + (ct + 1) * TN + tid];
        }

        // stage D (stride 130 floats)
        {
            int g = lane >> 2, t4 = lane & 3;
#pragma unroll
            for (int nt = 0; nt < 16; nt++) {
                int c0 = nt * 8 + t4 * 2;
                *reinterpret_cast<float2*>(Dst + (m0 + g) * 130 + c0)     = make_float2(acc[nt][0], acc[nt][1]);
                *reinterpret_cast<float2*>(Dst + (m0 + g + 8) * 130 + c0) = make_float2(acc[nt][2], acc[nt][3]);
            }
        }
        __syncthreads();

        // ---- epilogue: 64 approx scores per thread ----
        {
            const float* dr = Dst + erow * 130 + ech * 64;
            const float* sq = sqs + buf * 128 + ech * 64;
            int colg = ct * TN + ech * 64;
#pragma unroll
            for (int j = 0; j < 32; j++) {
                float2 d = *reinterpret_cast<const float2*>(dr + j * 2);
                float sc0 = fmaf(-2.f, d.x, sq[j * 2]);
                float sc1 = fmaf(-2.f, d.y, sq[j * 2 + 1]);
                if (sc0 < rootD) { heap_insert(sc0, colg + j * 2, hD, hI, tid); rootD = hD[tid]; }
                if (sc1 < rootD) { heap_insert(sc1, colg + j * 2 + 1, hD, hI, tid); rootD = hD[tid]; }
            }
        }
    }

    __syncthreads();
    // write 24 candidates per half
    {
        int row = b * NN + row0 + erow;
#pragma unroll
        for (int j = 0; j < KH; j++)
            g_cand[(size_t)row * NCAND + ech * KH + j] = hI[j * 256 + tid];
    }
}

// ===================== kernel B2: exact rescoring of 48 candidates -> top-20 =====================
__global__ void __launch_bounds__(256) rerank_kernel() {
    __shared__ float sc[8][NCAND];
    __shared__ int   sidx[8][NCAND];
    int w = threadIdx.x >> 5, lane = threadIdx.x & 31;
    int p = blockIdx.x * 8 + w;
    int bbase = (p >> 12) << 12;

    // load candidate list
    {
        int c = g_cand[(size_t)p * NCAND + lane];
        sidx[w][lane] = c;
        if (lane < 16) sidx[w][32 + lane] = g_cand[(size_t)p * NCAND + 32 + lane];
    }
    __syncwarp();

    int g = lane >> 3, k = lane & 7;
    const float* xr = g_xp + (size_t)p * CC + k * 8;
    float4 r0 = *reinterpret_cast<const float4*>(xr);
    float4 r1 = *reinterpret_cast<const float4*>(xr + 4);

#pragma unroll 3
    for (int batch = 0; batch < NCAND / 4; batch++) {
        int c = sidx[w][batch * 4 + g];
        const float* xc = g_xp + (size_t)(bbase + c) * CC + k * 8;
        float4 a0 = *reinterpret_cast<const float4*>(xc);
        float4 a1 = *reinterpret_cast<const float4*>(xc + 4);
        float d = r0.x * a0.x;
        d = fmaf(r0.y, a0.y, d);
        d = fmaf(r0.z, a0.z, d);
        d = fmaf(r0.w, a0.w, d);
        d = fmaf(r1.x, a1.x, d);
        d = fmaf(r1.y, a1.y, d);
        d = fmaf(r1.z, a1.z, d);
        d = fmaf(r1.w, a1.w, d);
        d += __shfl_xor_sync(0xffffffffu, d, 4);
        d += __shfl_xor_sync(0xffffffffu, d, 2);
        d += __shfl_xor_sync(0xffffffffu, d, 1);
        if (k == 0) sc[w][batch * 4 + g] = fmaf(-2.f, d, g_sq[bbase + c]);
    }
    __syncwarp();

    // all-pairs rank counting (strict total order via idx tiebreak)
    float sA = sc[w][lane];
    int   iA = sidx[w][lane];
    float sB = (lane < 16) ? sc[w][32 + lane] : 3.0e38f;
    int   iB = (lane < 16) ? sidx[w][32 + lane] : 0x7fffffff;
    int rA = 0, rB = 0;
#pragma unroll
    for (int j = 0; j < NCAND; j++) {
        float s = sc[w][j];
        int ji = sidx[w][j];
        rA += (s < sA) || (s == sA && ji < iA);
        rB += (s < sB) || (s == sB && ji < iB);
    }
    if (rA < KK) g_idx[(size_t)p * KK + rA] = iA;
    if (lane < 16 && rB < KK) g_idx[(size_t)p * KK + rB] = iB;
}

// ===================== kernel C: u = W1 @ x, v = (W2-W1) @ x =====================
__global__ void __launch_bounds__(128) gemm_uv_kernel(const float* __restrict__ x,
                                                      const float* __restrict__ W) {
    int b = blockIdx.z, og = blockIdx.y;
    int n = blockIdx.x * 128 + threadIdx.x;

    __shared__ float W1s[16][64];
    __shared__ float Wds[16][64];
    for (int i = threadIdx.x; i < 16 * 64; i += 128) {
        int oo = i >> 6, c = i & 63;
        int o = og * 16 + oo;
        float w1 = W[o * 2 * CC + c];
        float w2 = W[o * 2 * CC + CC + c];
        W1s[oo][c] = w1;
        Wds[oo][c] = w2 - w1;
    }
    __syncthreads();

    float ua[16], va[16];
#pragma unroll
    for (int oo = 0; oo < 16; oo++) { ua[oo] = 0.f; va[oo] = 0.f; }

    const float* xb = x + (size_t)b * CC * NN + n;
#pragma unroll
    for (int ch = 0; ch < CC; ch++) {
        float xv = xb[(size_t)ch * NN];
#pragma unroll
        for (int oo = 0; oo < 16; oo++) {
            ua[oo] = fmaf(W1s[oo][ch], xv, ua[oo]);
            va[oo] = fmaf(Wds[oo][ch], xv, va[oo]);
        }
    }

    float* up = g_u + ((size_t)b * NN + n) * OUTC + og * 16;
    float* vp = g_v + ((size_t)b * NN + n) * OUTC + og * 16;
#pragma unroll
    for (int oo = 0; oo < 16; oo += 4) {
        *reinterpret_cast<float4*>(up + oo) = make_float4(ua[oo], ua[oo + 1], ua[oo + 2], ua[oo + 3]);
        *reinterpret_cast<float4*>(vp + oo) = make_float4(va[oo], va[oo + 1], va[oo + 2], va[oo + 3]);
    }
}

// ===================== kernel D: edges =====================
__global__ void __launch_bounds__(256) edge_kernel() {
    __shared__ float ssum[OUTC];
    __shared__ float ssq[OUTC];
    int tid = threadIdx.x, lane = tid & 31, wrp = tid >> 5;
    if (tid < OUTC) { ssum[tid] = 0.f; ssq[tid] = 0.f; }
    __syncthreads();

    int p0 = blockIdx.x * 64;
    float lsum0 = 0.f, lsq0 = 0.f, lsum1 = 0.f, lsq1 = 0.f;

    for (int i = 0; i < 8; i++) {
        int p = p0 + wrp * 8 + i;
        const float* vp = g_v + (size_t)p * OUTC;
        float v0 = vp[lane], v1 = vp[lane + 32];
        int idxv = 0;
        if (lane < KK) idxv = g_idx[(size_t)p * KK + lane];
        int bbase = (p >> 12) << 12;

        float mx0 = -3.0e38f, mn0 = 3.0e38f, mx1 = -3.0e38f, mn1 = 3.0e38f;
#pragma unroll
        for (int k = 0; k < KK; k++) {
            int j = __shfl_sync(0xffffffffu, idxv, k);
            const float* uj = g_u + (size_t)(bbase + j) * OUTC;
            float z0 = uj[lane] + v0;
            float z1 = uj[lane + 32] + v1;
            mx0 = fmaxf(mx0, z0); mn0 = fminf(mn0, z0);
            mx1 = fmaxf(mx1, z1); mn1 = fminf(mn1, z1);
            lsum0 += z0; lsq0 = fmaf(z0, z0, lsq0);
            lsum1 += z1; lsq1 = fmaf(z1, z1, lsq1);
        }
        float* mxp = g_mx + (size_t)p * OUTC;
        float* mnp = g_mn + (size_t)p * OUTC;
        mxp[lane] = mx0; mxp[lane + 32] = mx1;
        mnp[lane] = mn0; mnp[lane + 32] = mn1;
    }

    atomicAdd(&ssum[lane], lsum0);
    atomicAdd(&ssum[lane + 32], lsum1);
    atomicAdd(&ssq[lane], lsq0);
    atomicAdd(&ssq[lane + 32], lsq1);
    __syncthreads();
    if (tid < OUTC) {
        atomicAdd(&g_sum[tid], ssum[tid]);
        atomicAdd(&g_sumsq[tid], ssq[tid]);
    }
}

// ===================== kernel E0: finalize BN affine =====================
__global__ void stats_kernel(const float* __restrict__ gamma, const float* __restrict__ beta) {
    int o = threadIdx.x;
    const float cnt = (float)((size_t)BB * NN * KK);
    float mean = g_sum[o] / cnt;
    float var = g_sumsq[o] / cnt - mean * mean;
    float s = gamma[o] * rsqrtf(var + 1e-5f);
    g_s[o] = s;
    g_t[o] = fmaf(-mean, s, beta[o]);
}

// ===================== kernel E: BN + LeakyReLU + transpose =====================
__global__ void __launch_bounds__(256) out_kernel(float* __restrict__ out) {
    __shared__ float tile[64][65];
    __shared__ float ss[OUTC], tt[OUTC];
    int tid = threadIdx.x;
    if (tid < OUTC) { ss[tid] = g_s[tid]; tt[tid] = g_t[tid]; }
    __syncthreads();

    int p0 = blockIdx.x * 64;
    int b = p0 >> 12;
    int n0 = p0 & (NN - 1);

#pragma unroll
    for (int j = 0; j < 16; j++) {
        int i = tid + j * 256;
        int nn = i >> 6, o = i & 63;
        size_t base = (size_t)(p0 + nn) * OUTC + o;
        float s = ss[o];
        float z = (s >= 0.f) ? g_mx[base] : g_mn[base];
        float y = fmaf(s, z, tt[o]);
        y = (y >= 0.f) ? y : 0.2f * y;
        tile[o][nn] = y;
    }
    __syncthreads();
#pragma unroll
    for (int j = 0; j < 16; j++) {
        int i = tid + j * 256;
        int o = i >> 6, nn = i & 63;
        out[((size_t)(b * OUTC + o)) * NN + n0 + nn] = tile[o][nn];
    }
}

// ===================== launch =====================
extern "C" void kernel_launch(void* const* d_in, const int* in_sizes, int n_in,
                              void* d_out, int out_size) {
    const float* x     = (const float*)d_in[0];
    const float* W     = (const float*)d_in[1];
    const float* gamma = (const float*)d_in[2];
    const float* beta  = (const float*)d_in[3];
    float* out = (float*)d_out;

    cudaFuncSetAttribute(knn_mma_kernel, cudaFuncAttributeMaxDynamicSharedMemorySize, SM_TOTAL);

    prep_kernel<<<(BB * NN) / 128, 128>>>(x);
    knn_mma_kernel<<<dim3(NN / TM, BB), 256, SM_TOTAL>>>();
    rerank_kernel<<<(BB * NN) / 8, 256>>>();
    gemm_uv_kernel<<<dim3(NN / 128, 4, BB), 128>>>(x, W);
    edge_kernel<<<(BB * NN) / 64, 256>>>();
    stats_kernel<<<1, OUTC>>>(gamma, beta);
    out_kernel<<<(BB * NN) / 64, 256>>>(out);
}

// round 5
// speedup vs baseline: 1.7666x; 1.7666x over previous
#include <cuda_runtime.h>
#include <cuda_fp16.h>
#include <cstdint>

#define BB 8
#define CC 64
#define NN 4096
#define KK 20
#define NCAND 48
#define NTARGET 24
#define OUTC 64
#define TM 128
#define TN 128

// ===================== device scratch (allocation-free) =====================
__device__ __half g_hi[(size_t)BB * NN * CC];
__device__ float g_xp[(size_t)BB * NN * CC];          // point-major fp32 copy
__device__ float g_sq[BB * NN];
__device__ uint32_t g_dist[(size_t)BB * NN * NN];     // flipped-uint scores, 512MB
__device__ int   g_cand[(size_t)BB * NN * NCAND];
__device__ int   g_idx[BB * NN * KK];
__device__ float g_u[(size_t)BB * NN * OUTC];
__device__ float g_v[(size_t)BB * NN * OUTC];
__device__ float g_mx[(size_t)BB * NN * OUTC];
__device__ float g_mn[(size_t)BB * NN * OUTC];
__device__ float g_sum[OUTC];
__device__ float g_sumsq[OUTC];
__device__ float g_s[OUTC];
__device__ float g_t[OUTC];

// ===================== helpers =====================
__device__ __forceinline__ void ldsm_x4(uint32_t addr, uint32_t* r) {
    asm volatile("ldmatrix.sync.aligned.m8n8.x4.shared.b16 {%0,%1,%2,%3}, [%4];"
                 : "=r"(r[0]), "=r"(r[1]), "=r"(r[2]), "=r"(r[3]) : "r"(addr));
}
__device__ __forceinline__ void mma16816(float* d, const uint32_t* a, const uint32_t* b) {
    asm volatile("mma.sync.aligned.m16n8k16.row.col.f32.f16.f16.f32 "
                 "{%0,%1,%2,%3}, {%4,%5,%6,%7}, {%8,%9}, {%0,%1,%2,%3};"
                 : "+f"(d[0]), "+f"(d[1]), "+f"(d[2]), "+f"(d[3])
                 : "r"(a[0]), "r"(a[1]), "r"(a[2]), "r"(a[3]), "r"(b[0]), "r"(b[1]));
}
__device__ __forceinline__ uint32_t smem_u32(const void* p) {
    uint32_t a;
    asm("{ .reg .u64 t; cvta.to.shared.u64 t, %1; cvt.u32.u64 %0, t; }" : "=r"(a) : "l"(p));
    return a;
}
__device__ __forceinline__ uint32_t fflip(float f) {
    uint32_t u = __float_as_uint(f);
    uint32_t m = (u & 0x80000000u) ? 0xFFFFFFFFu : 0x80000000u;
    return u ^ m;
}

// ===================== kernel A: sq norms + fp16 hi + fp32 point-major =====================
__global__ void __launch_bounds__(128) prep_kernel(const float* __restrict__ x) {
    int p = blockIdx.x * 128 + threadIdx.x;
    int b = p >> 12;
    int n = p & (NN - 1);
    const float* xb = x + (size_t)b * CC * NN + n;
    float s = 0.f;
#pragma unroll
    for (int g = 0; g < 8; g++) {
        uint4 h4;
        unsigned short* hp = (unsigned short*)&h4;
        float vf[8];
#pragma unroll
        for (int e = 0; e < 8; e++) {
            float v = xb[(size_t)(g * 8 + e) * NN];
            vf[e] = v;
            s = fmaf(v, v, s);
            hp[e] = __half_as_ushort(__float2half_rn(v));
        }
        *reinterpret_cast<uint4*>(g_hi + (size_t)p * CC + g * 8) = h4;
        *reinterpret_cast<float4*>(g_xp + (size_t)p * CC + g * 8) =
            make_float4(vf[0], vf[1], vf[2], vf[3]);
        *reinterpret_cast<float4*>(g_xp + (size_t)p * CC + g * 8 + 4) =
            make_float4(vf[4], vf[5], vf[6], vf[7]);
    }
    g_sq[p] = s;
    if (blockIdx.x == 0 && threadIdx.x < OUTC) {
        g_sum[threadIdx.x] = 0.f;
        g_sumsq[threadIdx.x] = 0.f;
    }
}

// ===================== kernel B1: HMMA GEMM -> flipped scores to gmem =====================
#define SM_A     0          /* 128*144 = 18432 */
#define SM_B     18432      /* 2*18432 = 36864 */
#define SM_DST   55296      /* 128*132*4 = 67584 */
#define SM_SQS   122880     /* 2*128*4 = 1024 */
#define SM_TOTAL 123904

__global__ void __launch_bounds__(256, 1) knn_gemm_kernel() {
    extern __shared__ char sm[];
    const uint32_t smb = smem_u32(sm);
    const int tid = threadIdx.x;
    const int wid = tid >> 5;
    const int lane = tid & 31;
    const int b = blockIdx.y;
    const int row0 = blockIdx.x * TM;

    const __half* hi_b = g_hi + (size_t)b * NN * CC;
    float* Dst = (float*)(sm + SM_DST);
    float* sqs = (float*)(sm + SM_SQS);

    // load A rows, padded stride 144B
    for (int t = 0; t < 4; t++) {
        int i = tid + t * 256;
        int m = i >> 3, j = i & 7;
        *reinterpret_cast<uint4*>(sm + SM_A + m * 144 + j * 16) =
            *reinterpret_cast<const uint4*>(hi_b + (size_t)(row0 + m) * CC + j * 8);
    }
    // B tile 0
    for (int t = 0; t < 4; t++) {
        int i = tid + t * 256;
        int n = i >> 3, j = i & 7;
        *reinterpret_cast<uint4*>(sm + SM_B + n * 144 + j * 16) =
            *reinterpret_cast<const uint4*>(hi_b + (size_t)n * CC + j * 8);
    }
    if (tid < 128) sqs[tid] = g_sq[b * NN + tid];
    __syncthreads();

    const int m0 = wid * 16;
    uint4 pre[4];
    float sqnext = 0.f;

    for (int ct = 0; ct < NN / TN; ct++) {
        int buf = ct & 1;
        uint32_t bsm = smb + SM_B + (uint32_t)buf * 18432u;

        // prefetch next B tile + sq to registers (overlaps MMA)
        if (ct + 1 < NN / TN) {
            int col0 = (ct + 1) * TN;
#pragma unroll
            for (int t = 0; t < 4; t++) {
                int i = tid + t * 256;
                int n = i >> 3, j = i & 7;
                pre[t] = *reinterpret_cast<const uint4*>(hi_b + (size_t)(col0 + n) * CC + j * 8);
            }
            if (tid < 128) sqnext = g_sq[b * NN + col0 + tid];
        }

        // ---- MMA: D[128x128] = A(128x64) . B^T(64x128) ----
        float acc[16][4];
#pragma unroll
        for (int nt = 0; nt < 16; nt++)
#pragma unroll
            for (int e = 0; e < 4; e++) acc[nt][e] = 0.f;

#pragma unroll
        for (int ks = 0; ks < 4; ks++) {
            uint32_t ah[4];
            uint32_t aoff = (uint32_t)(m0 + (lane & 15)) * 144u +
                            (uint32_t)(ks * 16 + ((lane >> 4) << 3)) * 2u;
            ldsm_x4(smb + SM_A + aoff, ah);
#pragma unroll
            for (int ntp = 0; ntp < 8; ntp++) {
                uint32_t bh[4];
                uint32_t bn = (uint32_t)(ntp * 16 + ((lane >> 4) << 3) + (lane & 7));
                uint32_t bk = (uint32_t)(ks * 16 + (((lane >> 3) & 1) << 3));
                ldsm_x4(bsm + bn * 144u + bk * 2u, bh);
                mma16816(acc[2 * ntp],     ah, bh);
                mma16816(acc[2 * ntp + 1], ah, bh + 2);
            }
        }

        __syncthreads();   // MMA done reading B[buf]; prev copy-out done reading Dst

        // store next B tile + sqs
        if (ct + 1 < NN / TN) {
            char* dstb = sm + SM_B + (buf ^ 1) * 18432;
#pragma unroll
            for (int t = 0; t < 4; t++) {
                int i = tid + t * 256;
                int n = i >> 3, j = i & 7;
                *reinterpret_cast<uint4*>(dstb + n * 144 + j * 16) = pre[t];
            }
            if (tid < 128) sqs[(buf ^ 1) * 128 + tid] = sqnext;
        }

        // stage D (stride 132 floats)
        {
            int g = lane >> 2, t4 = lane & 3;
#pragma unroll
            for (int nt = 0; nt < 16; nt++) {
                int c0 = nt * 8 + t4 * 2;
                *reinterpret_cast<float2*>(Dst + (m0 + g) * 132 + c0)     = make_float2(acc[nt][0], acc[nt][1]);
                *reinterpret_cast<float2*>(Dst + (m0 + g + 8) * 132 + c0) = make_float2(acc[nt][2], acc[nt][3]);
            }
        }
        __syncthreads();

        // ---- copy-out: score + flip + coalesced store (16 rows per warp) ----
        {
            float4 sq4 = *reinterpret_cast<const float4*>(sqs + buf * 128 + lane * 4);
            uint32_t* dout = g_dist + ((size_t)(b * NN) + row0) * NN + ct * TN + lane * 4;
#pragma unroll
            for (int rr = 0; rr < 16; rr++) {
                int wr = wid * 16 + rr;
                float4 d = *reinterpret_cast<const float4*>(Dst + wr * 132 + lane * 4);
                uint4 o;
                o.x = fflip(fmaf(-2.f, d.x, sq4.x));
                o.y = fflip(fmaf(-2.f, d.y, sq4.y));
                o.z = fflip(fmaf(-2.f, d.z, sq4.z));
                o.w = fflip(fmaf(-2.f, d.w, sq4.w));
                *reinterpret_cast<uint4*>(dout + (size_t)wr * NN) = o;
            }
        }
    }
}

// ===================== kernel B2: radix-select top-~24 per row =====================
__global__ void __launch_bounds__(128) select_kernel() {
    __shared__ uint32_t hist[256];
    __shared__ uint32_t sh_b, sh_cumb, sh_cumi;
    __shared__ uint32_t counter;

    const int tid = threadIdx.x;
    const int p = blockIdx.x;
    const uint32_t* row = g_dist + (size_t)p * NN;

    // load 32 scores per thread (coalesced uint4), cols = 4*(j*128+tid)+e
    uint4 v[8];
#pragma unroll
    for (int j = 0; j < 8; j++)
        v[j] = *reinterpret_cast<const uint4*>(row + 4 * (j * 128 + tid));

    uint32_t prefix = 0, lo = 0;
    uint64_t cut = 0;

#pragma unroll 1
    for (int level = 0; level < 4; level++) {
        int shift = 24 - 8 * level;
        hist[tid] = 0; hist[tid + 128] = 0;
        __syncthreads();
#pragma unroll
        for (int j = 0; j < 8; j++) {
            const uint32_t* u4 = (const uint32_t*)&v[j];
#pragma unroll
            for (int e = 0; e < 4; e++) {
                uint32_t u = u4[e];
                bool m = (level == 0) || ((u >> (shift + 8)) == (prefix >> (shift + 8)));
                if (m) atomicAdd(&hist[(u >> shift) & 255], 1);
            }
        }
        __syncthreads();
        if (tid == 0) {
            uint32_t cum = 0;
            int bb = 0;
            for (; bb < 256; bb++) {
                uint32_t h = hist[bb];
                if (lo + cum + h >= NTARGET) break;
                cum += h;
            }
            sh_b = bb; sh_cumb = cum; sh_cumi = cum + hist[bb];
        }
        __syncthreads();
        uint32_t bb = sh_b, cumb = sh_cumb, cumi = sh_cumi;
        if (lo + cumi <= NCAND || level == 3) {
            cut = ((uint64_t)prefix | ((uint64_t)bb << shift)) + (1ull << shift);
            break;
        }
        prefix |= bb << shift;
        lo += cumb;
        __syncthreads();
    }

    if (tid == 0) counter = 0;
    __syncthreads();

    int* cand = g_cand + (size_t)p * NCAND;
#pragma unroll
    for (int j = 0; j < 8; j++) {
        const uint32_t* u4 = (const uint32_t*)&v[j];
#pragma unroll
        for (int e = 0; e < 4; e++) {
            if ((uint64_t)u4[e] < cut) {
                uint32_t slot = atomicAdd(&counter, 1);
                if (slot < NCAND) cand[slot] = 4 * (j * 128 + tid) + e;
            }
        }
    }
    __syncthreads();
    uint32_t c = counter < NCAND ? counter : NCAND;
    for (int i = c + tid; i < NCAND; i += 128) cand[i] = -1;
}

// ===================== kernel B3: exact rescoring of <=48 candidates -> top-20 =====================
__global__ void __launch_bounds__(256) rerank_kernel() {
    __shared__ float sc[8][NCAND];
    __shared__ int   sidx[8][NCAND];
    int w = threadIdx.x >> 5, lane = threadIdx.x & 31;
    int p = blockIdx.x * 8 + w;
    int bbase = (p >> 12) << 12;

    sidx[w][lane] = g_cand[(size_t)p * NCAND + lane];
    if (lane < 16) sidx[w][32 + lane] = g_cand[(size_t)p * NCAND + 32 + lane];
    __syncwarp();

    int g = lane >> 3, k = lane & 7;
    const float* xr = g_xp + (size_t)p * CC + k * 8;
    float4 r0 = *reinterpret_cast<const float4*>(xr);
    float4 r1 = *reinterpret_cast<const float4*>(xr + 4);

#pragma unroll 3
    for (int batch = 0; batch < NCAND / 4; batch++) {
        int c = sidx[w][batch * 4 + g];
        int cc = (c < 0) ? 0 : c;
        const float* xc = g_xp + (size_t)(bbase + cc) * CC + k * 8;
        float4 a0 = *reinterpret_cast<const float4*>(xc);
        float4 a1 = *reinterpret_cast<const float4*>(xc + 4);
        float d = r0.x * a0.x;
        d = fmaf(r0.y, a0.y, d);
        d = fmaf(r0.z, a0.z, d);
        d = fmaf(r0.w, a0.w, d);
        d = fmaf(r1.x, a1.x, d);
        d = fmaf(r1.y, a1.y, d);
        d = fmaf(r1.z, a1.z, d);
        d = fmaf(r1.w, a1.w, d);
        d += __shfl_xor_sync(0xffffffffu, d, 4);
        d += __shfl_xor_sync(0xffffffffu, d, 2);
        d += __shfl_xor_sync(0xffffffffu, d, 1);
        if (k == 0) sc[w][batch * 4 + g] = (c < 0) ? 3.0e38f : fmaf(-2.f, d, g_sq[bbase + cc]);
    }
    __syncwarp();

    // all-pairs rank counting (strict total order via idx tiebreak)
    float sA = sc[w][lane];
    int   iA = sidx[w][lane];
    float sB = (lane < 16) ? sc[w][32 + lane] : 3.0e38f;
    int   iB = (lane < 16) ? sidx[w][32 + lane] : 0x7fffffff;
    int rA = 0, rB = 0;
#pragma unroll
    for (int j = 0; j < NCAND; j++) {
        float s = sc[w][j];
        int ji = sidx[w][j];
        rA += (s < sA) || (s == sA && ji < iA);
        rB += (s < sB) || (s == sB && ji < iB);
    }
    if (rA < KK) g_idx[(size_t)p * KK + rA] = iA;
    if (lane < 16 && rB < KK) g_idx[(size_t)p * KK + rB] = iB;
}

// ===================== kernel C: u = W1 @ x, v = (W2-W1) @ x =====================
__global__ void __launch_bounds__(128) gemm_uv_kernel(const float* __restrict__ x,
                                                      const float* __restrict__ W) {
    int b = blockIdx.z, og = blockIdx.y;
    int n = blockIdx.x * 128 + threadIdx.x;

    __shared__ float W1s[16][64];
    __shared__ float Wds[16][64];
    for (int i = threadIdx.x; i < 16 * 64; i += 128) {
        int oo = i >> 6, c = i & 63;
        int o = og * 16 + oo;
        float w1 = W[o * 2 * CC + c];
        float w2 = W[o * 2 * CC + CC + c];
        W1s[oo][c] = w1;
        Wds[oo][c] = w2 - w1;
    }
    __syncthreads();

    float ua[16], va[16];
#pragma unroll
    for (int oo = 0; oo < 16; oo++) { ua[oo] = 0.f; va[oo] = 0.f; }

    const float* xb = x + (size_t)b * CC * NN + n;
#pragma unroll
    for (int ch = 0; ch < CC; ch++) {
        float xv = xb[(size_t)ch * NN];
#pragma unroll
        for (int oo = 0; oo < 16; oo++) {
            ua[oo] = fmaf(W1s[oo][ch], xv, ua[oo]);
            va[oo] = fmaf(Wds[oo][ch], xv, va[oo]);
        }
    }

    float* up = g_u + ((size_t)b * NN + n) * OUTC + og * 16;
    float* vp = g_v + ((size_t)b * NN + n) * OUTC + og * 16;
#pragma unroll
    for (int oo = 0; oo < 16; oo += 4) {
        *reinterpret_cast<float4*>(up + oo) = make_float4(ua[oo], ua[oo + 1], ua[oo + 2], ua[oo + 3]);
        *reinterpret_cast<float4*>(vp + oo) = make_float4(va[oo], va[oo + 1], va[oo + 2], va[oo + 3]);
    }
}

// ===================== kernel D: edges =====================
__global__ void __launch_bounds__(256) edge_kernel() {
    __shared__ float ssum[OUTC];
    __shared__ float ssq[OUTC];
    int tid = threadIdx.x, lane = tid & 31, wrp = tid >> 5;
    if (tid < OUTC) { ssum[tid] = 0.f; ssq[tid] = 0.f; }
    __syncthreads();

    int p0 = blockIdx.x * 64;
    float lsum0 = 0.f, lsq0 = 0.f, lsum1 = 0.f, lsq1 = 0.f;

    for (int i = 0; i < 8; i++) {
        int p = p0 + wrp * 8 + i;
        const float* vp = g_v + (size_t)p * OUTC;
        float v0 = vp[lane], v1 = vp[lane + 32];
        int idxv = 0;
        if (lane < KK) idxv = g_idx[(size_t)p * KK + lane];
        int bbase = (p >> 12) << 12;

        float mx0 = -3.0e38f, mn0 = 3.0e38f, mx1 = -3.0e38f, mn1 = 3.0e38f;
#pragma unroll
        for (int k = 0; k < KK; k++) {
            int j = __shfl_sync(0xffffffffu, idxv, k);
            const float* uj = g_u + (size_t)(bbase + j) * OUTC;
            float z0 = uj[lane] + v0;
            float z1 = uj[lane + 32] + v1;
            mx0 = fmaxf(mx0, z0); mn0 = fminf(mn0, z0);
            mx1 = fmaxf(mx1, z1); mn1 = fminf(mn1, z1);
            lsum0 += z0; lsq0 = fmaf(z0, z0, lsq0);
            lsum1 += z1; lsq1 = fmaf(z1, z1, lsq1);
        }
        float* mxp = g_mx + (size_t)p * OUTC;
        float* mnp = g_mn + (size_t)p * OUTC;
        mxp[lane] = mx0; mxp[lane + 32] = mx1;
        mnp[lane] = mn0; mnp[lane + 32] = mn1;
    }

    atomicAdd(&ssum[lane], lsum0);
    atomicAdd(&ssum[lane + 32], lsum1);
    atomicAdd(&ssq[lane], lsq0);
    atomicAdd(&ssq[lane + 32], lsq1);
    __syncthreads();
    if (tid < OUTC) {
        atomicAdd(&g_sum[tid], ssum[tid]);
        atomicAdd(&g_sumsq[tid], ssq[tid]);
    }
}

// ===================== kernel E0: finalize BN affine =====================
__global__ void stats_kernel(const float* __restrict__ gamma, const float* __restrict__ beta) {
    int o = threadIdx.x;
    const float cnt = (float)((size_t)BB * NN * KK);
    float mean = g_sum[o] / cnt;
    float var = g_sumsq[o] / cnt - mean * mean;
    float s = gamma[o] * rsqrtf(var + 1e-5f);
    g_s[o] = s;
    g_t[o] = fmaf(-mean, s, beta[o]);
}

// ===================== kernel E: BN + LeakyReLU + transpose =====================
__global__ void __launch_bounds__(256) out_kernel(float* __restrict__ out) {
    __shared__ float tile[64][65];
    __shared__ float ss[OUTC], tt[OUTC];
    int tid = threadIdx.x;
    if (tid < OUTC) { ss[tid] = g_s[tid]; tt[tid] = g_t[tid]; }
    __syncthreads();

    int p0 = blockIdx.x * 64;
    int b = p0 >> 12;
    int n0 = p0 & (NN - 1);

#pragma unroll
    for (int j = 0; j < 16; j++) {
        int i = tid + j * 256;
        int nn = i >> 6, o = i & 63;
        size_t base = (size_t)(p0 + nn) * OUTC + o;
        float s = ss[o];
        float z = (s >= 0.f) ? g_mx[base] : g_mn[base];
        float y = fmaf(s, z, tt[o]);
        y = (y >= 0.f) ? y : 0.2f * y;
        tile[o][nn] = y;
    }
    __syncthreads();
#pragma unroll
    for (int j = 0; j < 16; j++) {
        int i = tid + j * 256;
        int o = i >> 6, nn = i & 63;
        out[((size_t)(b * OUTC + o)) * NN + n0 + nn] = tile[o][nn];
    }
}

// ===================== launch =====================
extern "C" void kernel_launch(void* const* d_in, const int* in_sizes, int n_in,
                              void* d_out, int out_size) {
    const float* x     = (const float*)d_in[0];
    const float* W     = (const float*)d_in[1];
    const float* gamma = (const float*)d_in[2];
    const float* beta  = (const float*)d_in[3];
    float* out = (float*)d_out;

    cudaFuncSetAttribute(knn_gemm_kernel, cudaFuncAttributeMaxDynamicSharedMemorySize, SM_TOTAL);

    prep_kernel<<<(BB * NN) / 128, 128>>>(x);
    knn_gemm_kernel<<<dim3(NN / TM, BB), 256, SM_TOTAL>>>();
    select_kernel<<<BB * NN, 128>>>();
    rerank_kernel<<<(BB * NN) / 8, 256>>>();
    gemm_uv_kernel<<<dim3(NN / 128, 4, BB), 128>>>(x, W);
    edge_kernel<<<(BB * NN) / 64, 256>>>();
    stats_kernel<<<1, OUTC>>>(gamma, beta);
    out_kernel<<<(BB * NN) / 64, 256>>>(out);
}

// round 6
// speedup vs baseline: 2.1381x; 1.2103x over previous
#include <cuda_runtime.h>
#include <cuda_fp16.h>
#include <cstdint>

#define BB 8
#define CC 64
#define NN 4096
#define KK 20
#define NCAND 48
#define NTARGET 24
#define OUTC 64
#define TM 128
#define TN 128

// ===================== device scratch (allocation-free) =====================
__device__ __half g_hi[(size_t)BB * NN * CC];
__device__ float g_xp[(size_t)BB * NN * CC];          // point-major fp32 copy
__device__ float g_sq[BB * NN];
__device__ uint32_t g_dist[(size_t)BB * NN * NN];     // flipped-uint scores, 512MB
__device__ int   g_cand[(size_t)BB * NN * NCAND];
__device__ int   g_idx[BB * NN * KK];
__device__ float g_u[(size_t)BB * NN * OUTC];
__device__ float g_v[(size_t)BB * NN * OUTC];
__device__ float g_mx[(size_t)BB * NN * OUTC];
__device__ float g_mn[(size_t)BB * NN * OUTC];
__device__ float g_sum[OUTC];
__device__ float g_sumsq[OUTC];
__device__ float g_s[OUTC];
__device__ float g_t[OUTC];

// ===================== helpers =====================
__device__ __forceinline__ void ldsm_x4(uint32_t addr, uint32_t* r) {
    asm volatile("ldmatrix.sync.aligned.m8n8.x4.shared.b16 {%0,%1,%2,%3}, [%4];"
                 : "=r"(r[0]), "=r"(r[1]), "=r"(r[2]), "=r"(r[3]) : "r"(addr));
}
__device__ __forceinline__ void mma16816(float* d, const uint32_t* a, const uint32_t* b) {
    asm volatile("mma.sync.aligned.m16n8k16.row.col.f32.f16.f16.f32 "
                 "{%0,%1,%2,%3}, {%4,%5,%6,%7}, {%8,%9}, {%0,%1,%2,%3};"
                 : "+f"(d[0]), "+f"(d[1]), "+f"(d[2]), "+f"(d[3])
                 : "r"(a[0]), "r"(a[1]), "r"(a[2]), "r"(a[3]), "r"(b[0]), "r"(b[1]));
}
__device__ __forceinline__ uint32_t smem_u32(const void* p) {
    uint32_t a;
    asm("{ .reg .u64 t; cvta.to.shared.u64 t, %1; cvt.u32.u64 %0, t; }" : "=r"(a) : "l"(p));
    return a;
}
__device__ __forceinline__ uint32_t fflip(float f) {
    uint32_t u = __float_as_uint(f);
    uint32_t m = (u & 0x80000000u) ? 0xFFFFFFFFu : 0x80000000u;
    return u ^ m;
}

// ===================== kernel A: sq norms + fp16 hi + fp32 point-major =====================
__global__ void __launch_bounds__(128) prep_kernel(const float* __restrict__ x) {
    int p = blockIdx.x * 128 + threadIdx.x;
    int b = p >> 12;
    int n = p & (NN - 1);
    const float* xb = x + (size_t)b * CC * NN + n;
    float s = 0.f;
#pragma unroll
    for (int g = 0; g < 8; g++) {
        uint4 h4;
        unsigned short* hp = (unsigned short*)&h4;
        float vf[8];
#pragma unroll
        for (int e = 0; e < 8; e++) {
            float v = xb[(size_t)(g * 8 + e) * NN];
            vf[e] = v;
            s = fmaf(v, v, s);
            hp[e] = __half_as_ushort(__float2half_rn(v));
        }
        *reinterpret_cast<uint4*>(g_hi + (size_t)p * CC + g * 8) = h4;
        *reinterpret_cast<float4*>(g_xp + (size_t)p * CC + g * 8) =
            make_float4(vf[0], vf[1], vf[2], vf[3]);
        *reinterpret_cast<float4*>(g_xp + (size_t)p * CC + g * 8 + 4) =
            make_float4(vf[4], vf[5], vf[6], vf[7]);
    }
    g_sq[p] = s;
    if (blockIdx.x == 0 && threadIdx.x < OUTC) {
        g_sum[threadIdx.x] = 0.f;
        g_sumsq[threadIdx.x] = 0.f;
    }
}

// ===================== kernel B1: HMMA GEMM -> flipped scores direct to gmem =====================
#define SM_A     0          /* 128*144 = 18432 */
#define SM_B     18432      /* 2*18432 = 36864 */
#define SM_SQS   55296      /* 2*128*4 = 1024 */
#define SM_TOTAL 56320

__global__ void __launch_bounds__(256, 2) knn_gemm_kernel() {
    extern __shared__ char sm[];
    const uint32_t smb = smem_u32(sm);
    const int tid = threadIdx.x;
    const int wid = tid >> 5;
    const int lane = tid & 31;
    const int b = blockIdx.y;
    const int row0 = blockIdx.x * TM;

    const __half* hi_b = g_hi + (size_t)b * NN * CC;
    float* sqs = (float*)(sm + SM_SQS);

    // load A rows, padded stride 144B
    for (int t = 0; t < 4; t++) {
        int i = tid + t * 256;
        int m = i >> 3, j = i & 7;
        *reinterpret_cast<uint4*>(sm + SM_A + m * 144 + j * 16) =
            *reinterpret_cast<const uint4*>(hi_b + (size_t)(row0 + m) * CC + j * 8);
    }
    // B tile 0
    for (int t = 0; t < 4; t++) {
        int i = tid + t * 256;
        int n = i >> 3, j = i & 7;
        *reinterpret_cast<uint4*>(sm + SM_B + n * 144 + j * 16) =
            *reinterpret_cast<const uint4*>(hi_b + (size_t)n * CC + j * 8);
    }
    if (tid < 128) sqs[tid] = g_sq[b * NN + tid];
    __syncthreads();

    const int m0 = wid * 16;
    const int g = lane >> 2, t4 = lane & 3;
    uint4 pre[4];
    float sqnext = 0.f;

    for (int ct = 0; ct < NN / TN; ct++) {
        int buf = ct & 1;
        uint32_t bsm = smb + SM_B + (uint32_t)buf * 18432u;

        // prefetch next B tile + sq to registers (overlaps MMA)
        if (ct + 1 < NN / TN) {
            int col0 = (ct + 1) * TN;
#pragma unroll
            for (int t = 0; t < 4; t++) {
                int i = tid + t * 256;
                int n = i >> 3, j = i & 7;
                pre[t] = *reinterpret_cast<const uint4*>(hi_b + (size_t)(col0 + n) * CC + j * 8);
            }
            if (tid < 128) sqnext = g_sq[b * NN + col0 + tid];
        }

        // ---- MMA: D[128x128] = A(128x64) . B^T(64x128) ----
        float acc[16][4];
#pragma unroll
        for (int nt = 0; nt < 16; nt++)
#pragma unroll
            for (int e = 0; e < 4; e++) acc[nt][e] = 0.f;

#pragma unroll
        for (int ks = 0; ks < 4; ks++) {
            uint32_t ah[4];
            uint32_t aoff = (uint32_t)(m0 + (lane & 15)) * 144u +
                            (uint32_t)(ks * 16 + ((lane >> 4) << 3)) * 2u;
            ldsm_x4(smb + SM_A + aoff, ah);
#pragma unroll
            for (int ntp = 0; ntp < 8; ntp++) {
                uint32_t bh[4];
                uint32_t bn = (uint32_t)(ntp * 16 + ((lane >> 4) << 3) + (lane & 7));
                uint32_t bk = (uint32_t)(ks * 16 + (((lane >> 3) & 1) << 3));
                ldsm_x4(bsm + bn * 144u + bk * 2u, bh);
                mma16816(acc[2 * ntp],     ah, bh);
                mma16816(acc[2 * ntp + 1], ah, bh + 2);
            }
        }

        __syncthreads();   // all MMA reads of B[buf^1 from prev iter] and sqs done

        // store next B tile + sqs (into buf^1, which MMA no longer reads)
        if (ct + 1 < NN / TN) {
            char* dstb = sm + SM_B + (buf ^ 1) * 18432;
#pragma unroll
            for (int t = 0; t < 4; t++) {
                int i = tid + t * 256;
                int n = i >> 3, j = i & 7;
                *reinterpret_cast<uint4*>(dstb + n * 144 + j * 16) = pre[t];
            }
            if (tid < 128) sqs[(buf ^ 1) * 128 + tid] = sqnext;
        }

        // ---- epilogue: score + flip + direct coalesced-sector stores ----
        {
            const float* sqb = sqs + buf * 128;
            uint32_t* dout = g_dist + ((size_t)(b * NN) + row0 + m0 + g) * NN + ct * TN;
#pragma unroll
            for (int nt = 0; nt < 16; nt++) {
                int c0 = nt * 8 + t4 * 2;
                float2 sq2 = *reinterpret_cast<const float2*>(sqb + c0);
                uint2 o0, o1;
                o0.x = fflip(fmaf(-2.f, acc[nt][0], sq2.x));
                o0.y = fflip(fmaf(-2.f, acc[nt][1], sq2.y));
                o1.x = fflip(fmaf(-2.f, acc[nt][2], sq2.x));
                o1.y = fflip(fmaf(-2.f, acc[nt][3], sq2.y));
                *reinterpret_cast<uint2*>(dout + c0) = o0;
                *reinterpret_cast<uint2*>(dout + (size_t)8 * NN + c0) = o1;
            }
        }
        __syncthreads();   // B[buf^1] fully written before next iteration's MMA
    }
}

// ===================== kernel B2: binary-search select top-[24,48] per row =====================
__global__ void __launch_bounds__(128) select_kernel() {
    __shared__ uint32_t wsum[2][4];
    __shared__ uint32_t counter;

    const int tid = threadIdx.x;
    const int wrp = tid >> 5;
    const int lane = tid & 31;
    const int p = blockIdx.x;
    const uint32_t* row = g_dist + (size_t)p * NN;

    // load 32 scores per thread (coalesced uint4)
    uint4 v[8];
#pragma unroll
    for (int j = 0; j < 8; j++)
        v[j] = *reinterpret_cast<const uint4*>(row + 4 * (j * 128 + tid));

    uint32_t lo = 0, hi = 0xFFFFFFFFu, cut = 0;
    bool found = false;

#pragma unroll 1
    for (int it = 0; it < 40; it++) {
        uint32_t mid = lo + ((hi - lo) >> 1);
        uint32_t c = 0;
#pragma unroll
        for (int j = 0; j < 8; j++) {
            const uint32_t* u4 = (const uint32_t*)&v[j];
            c += (u4[0] < mid) + (u4[1] < mid) + (u4[2] < mid) + (u4[3] < mid);
        }
        c = __reduce_add_sync(0xffffffffu, c);
        if (lane == 0) wsum[it & 1][wrp] = c;
        __syncthreads();
        uint32_t tot = wsum[it & 1][0] + wsum[it & 1][1] + wsum[it & 1][2] + wsum[it & 1][3];
        if (tot >= NTARGET && tot <= NCAND) { cut = mid; found = true; break; }
        if (tot >= NTARGET) hi = mid; else lo = mid;
        if (hi - lo <= 1) { cut = hi; found = true; break; }
    }
    if (!found) cut = hi;

    if (tid == 0) counter = 0;
    __syncthreads();

    int* cand = g_cand + (size_t)p * NCAND;
#pragma unroll
    for (int j = 0; j < 8; j++) {
        const uint32_t* u4 = (const uint32_t*)&v[j];
#pragma unroll
        for (int e = 0; e < 4; e++) {
            if (u4[e] < cut) {
                uint32_t slot = atomicAdd(&counter, 1);
                if (slot < NCAND) cand[slot] = 4 * (j * 128 + tid) + e;
            }
        }
    }
    __syncthreads();
    uint32_t c = counter < NCAND ? counter : NCAND;
    for (int i = c + tid; i < NCAND; i += 128) cand[i] = -1;
}

// ===================== kernel B3: exact rescoring of <=48 candidates -> top-20 =====================
__global__ void __launch_bounds__(256) rerank_kernel() {
    __shared__ float sc[8][NCAND];
    __shared__ int   sidx[8][NCAND];
    int w = threadIdx.x >> 5, lane = threadIdx.x & 31;
    int p = blockIdx.x * 8 + w;
    int bbase = (p >> 12) << 12;

    sidx[w][lane] = g_cand[(size_t)p * NCAND + lane];
    if (lane < 16) sidx[w][32 + lane] = g_cand[(size_t)p * NCAND + 32 + lane];
    __syncwarp();

    int g = lane >> 3, k = lane & 7;
    const float* xr = g_xp + (size_t)p * CC + k * 8;
    float4 r0 = *reinterpret_cast<const float4*>(xr);
    float4 r1 = *reinterpret_cast<const float4*>(xr + 4);

#pragma unroll 3
    for (int batch = 0; batch < NCAND / 4; batch++) {
        int c = sidx[w][batch * 4 + g];
        int cc = (c < 0) ? 0 : c;
        const float* xc = g_xp + (size_t)(bbase + cc) * CC + k * 8;
        float4 a0 = *reinterpret_cast<const float4*>(xc);
        float4 a1 = *reinterpret_cast<const float4*>(xc + 4);
        float d = r0.x * a0.x;
        d = fmaf(r0.y, a0.y, d);
        d = fmaf(r0.z, a0.z, d);
        d = fmaf(r0.w, a0.w, d);
        d = fmaf(r1.x, a1.x, d);
        d = fmaf(r1.y, a1.y, d);
        d = fmaf(r1.z, a1.z, d);
        d = fmaf(r1.w, a1.w, d);
        d += __shfl_xor_sync(0xffffffffu, d, 4);
        d += __shfl_xor_sync(0xffffffffu, d, 2);
        d += __shfl_xor_sync(0xffffffffu, d, 1);
        if (k == 0) sc[w][batch * 4 + g] = (c < 0) ? 3.0e38f : fmaf(-2.f, d, g_sq[bbase + cc]);
    }
    __syncwarp();

    float sA = sc[w][lane];
    int   iA = sidx[w][lane];
    float sB = (lane < 16) ? sc[w][32 + lane] : 3.0e38f;
    int   iB = (lane < 16) ? sidx[w][32 + lane] : 0x7fffffff;
    int rA = 0, rB = 0;
#pragma unroll
    for (int j = 0; j < NCAND; j++) {
        float s = sc[w][j];
        int ji = sidx[w][j];
        rA += (s < sA) || (s == sA && ji < iA);
        rB += (s < sB) || (s == sB && ji < iB);
    }
    if (rA < KK) g_idx[(size_t)p * KK + rA] = iA;
    if (lane < 16 && rB < KK) g_idx[(size_t)p * KK + rB] = iB;
}

// ===================== kernel C: u = W1 @ x, v = (W2-W1) @ x (8 outputs/thread) =====================
__global__ void __launch_bounds__(128) gemm_uv_kernel(const float* __restrict__ x,
                                                      const float* __restrict__ W) {
    int b = blockIdx.z, og = blockIdx.y;
    int n = blockIdx.x * 128 + threadIdx.x;

    __shared__ float W1s[8][64];
    __shared__ float Wds[8][64];
    for (int i = threadIdx.x; i < 8 * 64; i += 128) {
        int oo = i >> 6, c = i & 63;
        int o = og * 8 + oo;
        float w1 = W[o * 2 * CC + c];
        float w2 = W[o * 2 * CC + CC + c];
        W1s[oo][c] = w1;
        Wds[oo][c] = w2 - w1;
    }
    __syncthreads();

    float ua[8], va[8];
#pragma unroll
    for (int oo = 0; oo < 8; oo++) { ua[oo] = 0.f; va[oo] = 0.f; }

    const float* xb = x + (size_t)b * CC * NN + n;
#pragma unroll
    for (int ch = 0; ch < CC; ch++) {
        float xv = xb[(size_t)ch * NN];
#pragma unroll
        for (int oo = 0; oo < 8; oo++) {
            ua[oo] = fmaf(W1s[oo][ch], xv, ua[oo]);
            va[oo] = fmaf(Wds[oo][ch], xv, va[oo]);
        }
    }

    float* up = g_u + ((size_t)b * NN + n) * OUTC + og * 8;
    float* vp = g_v + ((size_t)b * NN + n) * OUTC + og * 8;
#pragma unroll
    for (int oo = 0; oo < 8; oo += 4) {
        *reinterpret_cast<float4*>(up + oo) = make_float4(ua[oo], ua[oo + 1], ua[oo + 2], ua[oo + 3]);
        *reinterpret_cast<float4*>(vp + oo) = make_float4(va[oo], va[oo + 1], va[oo + 2], va[oo + 3]);
    }
}

// ===================== kernel D: edges =====================
__global__ void __launch_bounds__(256) edge_kernel() {
    __shared__ float ssum[OUTC];
    __shared__ float ssq[OUTC];
    int tid = threadIdx.x, lane = tid & 31, wrp = tid >> 5;
    if (tid < OUTC) { ssum[tid] = 0.f; ssq[tid] = 0.f; }
    __syncthreads();

    int p0 = blockIdx.x * 64;
    float lsum0 = 0.f, lsq0 = 0.f, lsum1 = 0.f, lsq1 = 0.f;

    for (int i = 0; i < 8; i++) {
        int p = p0 + wrp * 8 + i;
        const float* vp = g_v + (size_t)p * OUTC;
        float v0 = vp[lane], v1 = vp[lane + 32];
        int idxv = 0;
        if (lane < KK) idxv = g_idx[(size_t)p * KK + lane];
        int bbase = (p >> 12) << 12;

        float mx0 = -3.0e38f, mn0 = 3.0e38f, mx1 = -3.0e38f, mn1 = 3.0e38f;
#pragma unroll
        for (int k = 0; k < KK; k++) {
            int j = __shfl_sync(0xffffffffu, idxv, k);
            const float* uj = g_u + (size_t)(bbase + j) * OUTC;
            float z0 = uj[lane] + v0;
            float z1 = uj[lane + 32] + v1;
            mx0 = fmaxf(mx0, z0); mn0 = fminf(mn0, z0);
            mx1 = fmaxf(mx1, z1); mn1 = fminf(mn1, z1);
            lsum0 += z0; lsq0 = fmaf(z0, z0, lsq0);
            lsum1 += z1; lsq1 = fmaf(z1, z1, lsq1);
        }
        float* mxp = g_mx + (size_t)p * OUTC;
        float* mnp = g_mn + (size_t)p * OUTC;
        mxp[lane] = mx0; mxp[lane + 32] = mx1;
        mnp[lane] = mn0; mnp[lane + 32] = mn1;
    }

    atomicAdd(&ssum[lane], lsum0);
    atomicAdd(&ssum[lane + 32], lsum1);
    atomicAdd(&ssq[lane], lsq0);
    atomicAdd(&ssq[lane + 32], lsq1);
    __syncthreads();
    if (tid < OUTC) {
        atomicAdd(&g_sum[tid], ssum[tid]);
        atomicAdd(&g_sumsq[tid], ssq[tid]);
    }
}

// ===================== kernel E0: finalize BN affine =====================
__global__ void stats_kernel(const float* __restrict__ gamma, const float* __restrict__ beta) {
    int o = threadIdx.x;
    const float cnt = (float)((size_t)BB * NN * KK);
    float mean = g_sum[o] / cnt;
    float var = g_sumsq[o] / cnt - mean * mean;
    float s = gamma[o] * rsqrtf(var + 1e-5f);
    g_s[o] = s;
    g_t[o] = fmaf(-mean, s, beta[o]);
}

// ===================== kernel E: BN + LeakyReLU + transpose =====================
__global__ void __launch_bounds__(256) out_kernel(float* __restrict__ out) {
    __shared__ float tile[64][65];
    __shared__ float ss[OUTC], tt[OUTC];
    int tid = threadIdx.x;
    if (tid < OUTC) { ss[tid] = g_s[tid]; tt[tid] = g_t[tid]; }
    __syncthreads();

    int p0 = blockIdx.x * 64;
    int b = p0 >> 12;
    int n0 = p0 & (NN - 1);

#pragma unroll
    for (int j = 0; j < 16; j++) {
        int i = tid + j * 256;
        int nn = i >> 6, o = i & 63;
        size_t base = (size_t)(p0 + nn) * OUTC + o;
        float s = ss[o];
        float z = (s >= 0.f) ? g_mx[base] : g_mn[base];
        float y = fmaf(s, z, tt[o]);
        y = (y >= 0.f) ? y : 0.2f * y;
        tile[o][nn] = y;
    }
    __syncthreads();
#pragma unroll
    for (int j = 0; j < 16; j++) {
        int i = tid + j * 256;
        int o = i >> 6, nn = i & 63;
        out[((size_t)(b * OUTC + o)) * NN + n0 + nn] = tile[o][nn];
    }
}

// ===================== launch =====================
extern "C" void kernel_launch(void* const* d_in, const int* in_sizes, int n_in,
                              void* d_out, int out_size) {
    const float* x     = (const float*)d_in[0];
    const float* W     = (const float*)d_in[1];
    const float* gamma = (const float*)d_in[2];
    const float* beta  = (const float*)d_in[3];
    float* out = (float*)d_out;

    cudaFuncSetAttribute(knn_gemm_kernel, cudaFuncAttributeMaxDynamicSharedMemorySize, SM_TOTAL);

    prep_kernel<<<(BB * NN) / 128, 128>>>(x);
    knn_gemm_kernel<<<dim3(NN / TM, BB), 256, SM_TOTAL>>>();
    select_kernel<<<BB * NN, 128>>>();
    rerank_kernel<<<(BB * NN) / 8, 256>>>();
    gemm_uv_kernel<<<dim3(NN / 128, 8, BB), 128>>>(x, W);
    edge_kernel<<<(BB * NN) / 64, 256>>>();
    stats_kernel<<<1, OUTC>>>(gamma, beta);
    out_kernel<<<(BB * NN) / 64, 256>>>(out);
}

// round 7
// speedup vs baseline: 2.4516x; 1.1466x over previous
#include <cuda_runtime.h>
#include <cuda_fp16.h>
#include <cstdint>

#define BB 8
#define CC 64
#define NN 4096
#define KK 20
#define NCAND 48
#define NTARGET 24
#define OUTC 64
#define TM 128
#define TN 128

// ===================== device scratch (allocation-free) =====================
__device__ __half g_hi[(size_t)BB * NN * CC];
__device__ float g_xp[(size_t)BB * NN * CC];          // point-major fp32 copy
__device__ float g_sq[BB * NN];
__device__ unsigned short g_scor[(size_t)BB * NN * NN];  // flipped-fp16 scores, 256MB
__device__ int   g_idx[BB * NN * KK];
__device__ float g_u[(size_t)BB * NN * OUTC];
__device__ float g_v[(size_t)BB * NN * OUTC];
__device__ float g_mx[(size_t)BB * NN * OUTC];
__device__ float g_mn[(size_t)BB * NN * OUTC];
__device__ float g_sum[OUTC];
__device__ float g_sumsq[OUTC];
__device__ float g_s[OUTC];
__device__ float g_t[OUTC];

// ===================== helpers =====================
__device__ __forceinline__ void ldsm_x4(uint32_t addr, uint32_t* r) {
    asm volatile("ldmatrix.sync.aligned.m8n8.x4.shared.b16 {%0,%1,%2,%3}, [%4];"
                 : "=r"(r[0]), "=r"(r[1]), "=r"(r[2]), "=r"(r[3]) : "r"(addr));
}
__device__ __forceinline__ void mma16816(float* d, const uint32_t* a, const uint32_t* b) {
    asm volatile("mma.sync.aligned.m16n8k16.row.col.f32.f16.f16.f32 "
                 "{%0,%1,%2,%3}, {%4,%5,%6,%7}, {%8,%9}, {%0,%1,%2,%3};"
                 : "+f"(d[0]), "+f"(d[1]), "+f"(d[2]), "+f"(d[3])
                 : "r"(a[0]), "r"(a[1]), "r"(a[2]), "r"(a[3]), "r"(b[0]), "r"(b[1]));
}
__device__ __forceinline__ uint32_t smem_u32(const void* p) {
    uint32_t a;
    asm("{ .reg .u64 t; cvta.to.shared.u64 t, %1; cvt.u32.u64 %0, t; }" : "=r"(a) : "l"(p));
    return a;
}
// two floats -> two flipped-fp16 (monotone: smaller float => smaller u16), packed
__device__ __forceinline__ uint32_t fflip16x2(float a, float b) {
    __half2 h2 = __floats2half2_rn(a, b);
    uint32_t u = *reinterpret_cast<uint32_t*>(&h2);
    uint32_t xorv = 0x80008000u | (((u >> 15) & 0x00010001u) * 0x7FFFu);
    return u ^ xorv;
}

// ===================== kernel A: sq norms + fp16 hi + fp32 point-major =====================
__global__ void __launch_bounds__(128) prep_kernel(const float* __restrict__ x) {
    int p = blockIdx.x * 128 + threadIdx.x;
    int b = p >> 12;
    int n = p & (NN - 1);
    const float* xb = x + (size_t)b * CC * NN + n;
    float s = 0.f;
#pragma unroll
    for (int g = 0; g < 8; g++) {
        uint4 h4;
        unsigned short* hp = (unsigned short*)&h4;
        float vf[8];
#pragma unroll
        for (int e = 0; e < 8; e++) {
            float v = xb[(size_t)(g * 8 + e) * NN];
            vf[e] = v;
            s = fmaf(v, v, s);
            hp[e] = __half_as_ushort(__float2half_rn(v));
        }
        *reinterpret_cast<uint4*>(g_hi + (size_t)p * CC + g * 8) = h4;
        *reinterpret_cast<float4*>(g_xp + (size_t)p * CC + g * 8) =
            make_float4(vf[0], vf[1], vf[2], vf[3]);
        *reinterpret_cast<float4*>(g_xp + (size_t)p * CC + g * 8 + 4) =
            make_float4(vf[4], vf[5], vf[6], vf[7]);
    }
    g_sq[p] = s;
    if (blockIdx.x == 0 && threadIdx.x < OUTC) {
        g_sum[threadIdx.x] = 0.f;
        g_sumsq[threadIdx.x] = 0.f;
    }
}

// ===================== kernel B1: HMMA GEMM -> flipped-fp16 scores to gmem =====================
#define SM_A     0          /* 128*144 = 18432 */
#define SM_B     18432      /* 2*18432 = 36864 */
#define SM_SQS   55296      /* 2*128*4 = 1024 */
#define SM_TOTAL 56320

__global__ void __launch_bounds__(256, 2) knn_gemm_kernel() {
    extern __shared__ char sm[];
    const uint32_t smb = smem_u32(sm);
    const int tid = threadIdx.x;
    const int wid = tid >> 5;
    const int lane = tid & 31;
    const int b = blockIdx.y;
    const int row0 = blockIdx.x * TM;

    const __half* hi_b = g_hi + (size_t)b * NN * CC;
    float* sqs = (float*)(sm + SM_SQS);

    // load A rows, padded stride 144B
    for (int t = 0; t < 4; t++) {
        int i = tid + t * 256;
        int m = i >> 3, j = i & 7;
        *reinterpret_cast<uint4*>(sm + SM_A + m * 144 + j * 16) =
            *reinterpret_cast<const uint4*>(hi_b + (size_t)(row0 + m) * CC + j * 8);
    }
    // B tile 0
    for (int t = 0; t < 4; t++) {
        int i = tid + t * 256;
        int n = i >> 3, j = i & 7;
        *reinterpret_cast<uint4*>(sm + SM_B + n * 144 + j * 16) =
            *reinterpret_cast<const uint4*>(hi_b + (size_t)n * CC + j * 8);
    }
    if (tid < 128) sqs[tid] = g_sq[b * NN + tid];
    __syncthreads();

    const int m0 = wid * 16;
    const int g = lane >> 2, t4 = lane & 3;
    uint4 pre[4];
    float sqnext = 0.f;

    for (int ct = 0; ct < NN / TN; ct++) {
        int buf = ct & 1;
        uint32_t bsm = smb + SM_B + (uint32_t)buf * 18432u;

        // prefetch next B tile + sq to registers (overlaps MMA)
        if (ct + 1 < NN / TN) {
            int col0 = (ct + 1) * TN;
#pragma unroll
            for (int t = 0; t < 4; t++) {
                int i = tid + t * 256;
                int n = i >> 3, j = i & 7;
                pre[t] = *reinterpret_cast<const uint4*>(hi_b + (size_t)(col0 + n) * CC + j * 8);
            }
            if (tid < 128) sqnext = g_sq[b * NN + col0 + tid];
        }

        // ---- MMA: D[128x128] = A(128x64) . B^T(64x128) ----
        float acc[16][4];
#pragma unroll
        for (int nt = 0; nt < 16; nt++)
#pragma unroll
            for (int e = 0; e < 4; e++) acc[nt][e] = 0.f;

#pragma unroll
        for (int ks = 0; ks < 4; ks++) {
            uint32_t ah[4];
            uint32_t aoff = (uint32_t)(m0 + (lane & 15)) * 144u +
                            (uint32_t)(ks * 16 + ((lane >> 4) << 3)) * 2u;
            ldsm_x4(smb + SM_A + aoff, ah);
#pragma unroll
            for (int ntp = 0; ntp < 8; ntp++) {
                uint32_t bh[4];
                uint32_t bn = (uint32_t)(ntp * 16 + ((lane >> 4) << 3) + (lane & 7));
                uint32_t bk = (uint32_t)(ks * 16 + (((lane >> 3) & 1) << 3));
                ldsm_x4(bsm + bn * 144u + bk * 2u, bh);
                mma16816(acc[2 * ntp],     ah, bh);
                mma16816(acc[2 * ntp + 1], ah, bh + 2);
            }
        }

        __syncthreads();

        // store next B tile + sqs
        if (ct + 1 < NN / TN) {
            char* dstb = sm + SM_B + (buf ^ 1) * 18432;
#pragma unroll
            for (int t = 0; t < 4; t++) {
                int i = tid + t * 256;
                int n = i >> 3, j = i & 7;
                *reinterpret_cast<uint4*>(dstb + n * 144 + j * 16) = pre[t];
            }
            if (tid < 128) sqs[(buf ^ 1) * 128 + tid] = sqnext;
        }

        // ---- epilogue: score + flip-to-u16 + direct stores ----
        {
            const float* sqb = sqs + buf * 128;
            unsigned short* dout = g_scor + ((size_t)(b * NN) + row0 + m0 + g) * NN + ct * TN;
#pragma unroll
            for (int nt = 0; nt < 16; nt++) {
                int c0 = nt * 8 + t4 * 2;
                float2 sq2 = *reinterpret_cast<const float2*>(sqb + c0);
                uint32_t o0 = fflip16x2(fmaf(-2.f, acc[nt][0], sq2.x),
                                        fmaf(-2.f, acc[nt][1], sq2.y));
                uint32_t o1 = fflip16x2(fmaf(-2.f, acc[nt][2], sq2.x),
                                        fmaf(-2.f, acc[nt][3], sq2.y));
                *reinterpret_cast<uint32_t*>(dout + c0) = o0;
                *reinterpret_cast<uint32_t*>(dout + (size_t)8 * NN + c0) = o1;
            }
        }
        __syncthreads();
    }
}

// ===================== kernel B2: fused select (binary search) + exact rerank =====================
__global__ void __launch_bounds__(128) select_rerank_kernel() {
    __shared__ uint32_t wsum[2][4];
    __shared__ uint32_t counter;
    __shared__ int   cidx[NCAND];
    __shared__ float csc[NCAND];

    const int tid = threadIdx.x;
    const int wrp = tid >> 5;
    const int lane = tid & 31;
    const int p = blockIdx.x;
    const uint4* r4 = reinterpret_cast<const uint4*>(g_scor + (size_t)p * NN);

    // load 32 u16 scores per thread (coalesced uint4)
    uint4 v[4];
#pragma unroll
    for (int j = 0; j < 4; j++) v[j] = r4[j * 128 + tid];

    uint32_t lo = 0, hi = 0x10000u, cut = 0x10000u;

#pragma unroll 1
    for (int it = 0; it < 17; it++) {
        uint32_t mid = (lo + hi) >> 1;
        uint32_t c = 0;
#pragma unroll
        for (int j = 0; j < 4; j++) {
            const uint32_t* u4 = (const uint32_t*)&v[j];
#pragma unroll
            for (int e = 0; e < 4; e++) {
                uint32_t u = u4[e];
                c += ((u & 0xFFFFu) < mid) + ((u >> 16) < mid);
            }
        }
        c = __reduce_add_sync(0xffffffffu, c);
        if (lane == 0) wsum[it & 1][wrp] = c;
        __syncthreads();
        uint32_t tot = wsum[it & 1][0] + wsum[it & 1][1] + wsum[it & 1][2] + wsum[it & 1][3];
        if (tot >= NTARGET && tot <= NCAND) { cut = mid; break; }
        if (tot >= NTARGET) hi = mid; else lo = mid;
        if (hi - lo <= 1) { cut = hi; break; }
    }

    if (tid == 0) counter = 0;
    __syncthreads();

    // compaction into smem
#pragma unroll
    for (int j = 0; j < 4; j++) {
        const uint32_t* u4 = (const uint32_t*)&v[j];
#pragma unroll
        for (int e = 0; e < 4; e++) {
            uint32_t u = u4[e];
            int i32 = 4 * (j * 128 + tid) + e;
            if ((u & 0xFFFFu) < cut) {
                uint32_t slot = atomicAdd(&counter, 1);
                if (slot < NCAND) cidx[slot] = 2 * i32;
            }
            if ((u >> 16) < cut) {
                uint32_t slot = atomicAdd(&counter, 1);
                if (slot < NCAND) cidx[slot] = 2 * i32 + 1;
            }
        }
    }
    __syncthreads();
    int cnt = counter < NCAND ? (int)counter : NCAND;
    int bbase = (p >> 12) << 12;

    // exact fp32 rescoring: one thread per candidate
    if (tid < NCAND) {
        if (tid < cnt) {
            int c = cidx[tid];
            const float* xr = g_xp + (size_t)p * CC;
            const float* xc = g_xp + (size_t)(bbase + c) * CC;
            float d = 0.f;
#pragma unroll
            for (int i = 0; i < 16; i++) {
                float4 a = *reinterpret_cast<const float4*>(xr + i * 4);
                float4 bq = *reinterpret_cast<const float4*>(xc + i * 4);
                d = fmaf(a.x, bq.x, d);
                d = fmaf(a.y, bq.y, d);
                d = fmaf(a.z, bq.z, d);
                d = fmaf(a.w, bq.w, d);
            }
            csc[tid] = fmaf(-2.f, d, g_sq[bbase + c]);
        } else {
            csc[tid] = 3.0e38f;
            cidx[tid] = 0x7fffffff;
        }
    }
    __syncthreads();

    // rank counting -> top-20
    if (tid < NCAND) {
        float s = csc[tid];
        int   ii = cidx[tid];
        int r = 0;
#pragma unroll
        for (int j = 0; j < NCAND; j++) {
            float sj = csc[j];
            int ij = cidx[j];
            r += (sj < s) || (sj == s && ij < ii);
        }
        if (r < KK) g_idx[(size_t)p * KK + r] = ii;
    }
}

// ===================== kernel C: u = W1 @ x, v = (W2-W1) @ x (8 outputs/thread) =====================
__global__ void __launch_bounds__(128) gemm_uv_kernel(const float* __restrict__ x,
                                                      const float* __restrict__ W) {
    int b = blockIdx.z, og = blockIdx.y;
    int n = blockIdx.x * 128 + threadIdx.x;

    __shared__ float W1s[8][64];
    __shared__ float Wds[8][64];
    for (int i = threadIdx.x; i < 8 * 64; i += 128) {
        int oo = i >> 6, c = i & 63;
        int o = og * 8 + oo;
        float w1 = W[o * 2 * CC + c];
        float w2 = W[o * 2 * CC + CC + c];
        W1s[oo][c] = w1;
        Wds[oo][c] = w2 - w1;
    }
    __syncthreads();

    float ua[8], va[8];
#pragma unroll
    for (int oo = 0; oo < 8; oo++) { ua[oo] = 0.f; va[oo] = 0.f; }

    const float* xb = x + (size_t)b * CC * NN + n;
#pragma unroll
    for (int ch = 0; ch < CC; ch++) {
        float xv = xb[(size_t)ch * NN];
#pragma unroll
        for (int oo = 0; oo < 8; oo++) {
            ua[oo] = fmaf(W1s[oo][ch], xv, ua[oo]);
            va[oo] = fmaf(Wds[oo][ch], xv, va[oo]);
        }
    }

    float* up = g_u + ((size_t)b * NN + n) * OUTC + og * 8;
    float* vp = g_v + ((size_t)b * NN + n) * OUTC + og * 8;
#pragma unroll
    for (int oo = 0; oo < 8; oo += 4) {
        *reinterpret_cast<float4*>(up + oo) = make_float4(ua[oo], ua[oo + 1], ua[oo + 2], ua[oo + 3]);
        *reinterpret_cast<float4*>(vp + oo) = make_float4(va[oo], va[oo + 1], va[oo + 2], va[oo + 3]);
    }
}

// ===================== kernel D: edges =====================
__global__ void __launch_bounds__(256) edge_kernel() {
    __shared__ float ssum[OUTC];
    __shared__ float ssq[OUTC];
    int tid = threadIdx.x, lane = tid & 31, wrp = tid >> 5;
    if (tid < OUTC) { ssum[tid] = 0.f; ssq[tid] = 0.f; }
    __syncthreads();

    int p0 = blockIdx.x * 64;
    float lsum0 = 0.f, lsq0 = 0.f, lsum1 = 0.f, lsq1 = 0.f;

    for (int i = 0; i < 8; i++) {
        int p = p0 + wrp * 8 + i;
        const float* vp = g_v + (size_t)p * OUTC;
        float v0 = vp[lane], v1 = vp[lane + 32];
        int idxv = 0;
        if (lane < KK) idxv = g_idx[(size_t)p * KK + lane];
        int bbase = (p >> 12) << 12;

        float mx0 = -3.0e38f, mn0 = 3.0e38f, mx1 = -3.0e38f, mn1 = 3.0e38f;
#pragma unroll
        for (int k = 0; k < KK; k++) {
            int j = __shfl_sync(0xffffffffu, idxv, k);
            const float* uj = g_u + (size_t)(bbase + j) * OUTC;
            float z0 = uj[lane] + v0;
            float z1 = uj[lane + 32] + v1;
            mx0 = fmaxf(mx0, z0); mn0 = fminf(mn0, z0);
            mx1 = fmaxf(mx1, z1); mn1 = fminf(mn1, z1);
            lsum0 += z0; lsq0 = fmaf(z0, z0, lsq0);
            lsum1 += z1; lsq1 = fmaf(z1, z1, lsq1);
        }
        float* mxp = g_mx + (size_t)p * OUTC;
        float* mnp = g_mn + (size_t)p * OUTC;
        mxp[lane] = mx0; mxp[lane + 32] = mx1;
        mnp[lane] = mn0; mnp[lane + 32] = mn1;
    }

    atomicAdd(&ssum[lane], lsum0);
    atomicAdd(&ssum[lane + 32], lsum1);
    atomicAdd(&ssq[lane], lsq0);
    atomicAdd(&ssq[lane + 32], lsq1);
    __syncthreads();
    if (tid < OUTC) {
        atomicAdd(&g_sum[tid], ssum[tid]);
        atomicAdd(&g_sumsq[tid], ssq[tid]);
    }
}

// ===================== kernel E0: finalize BN affine =====================
__global__ void stats_kernel(const float* __restrict__ gamma, const float* __restrict__ beta) {
    int o = threadIdx.x;
    const float cnt = (float)((size_t)BB * NN * KK);
    float mean = g_sum[o] / cnt;
    float var = g_sumsq[o] / cnt - mean * mean;
    float s = gamma[o] * rsqrtf(var + 1e-5f);
    g_s[o] = s;
    g_t[o] = fmaf(-mean, s, beta[o]);
}

// ===================== kernel E: BN + LeakyReLU + transpose =====================
__global__ void __launch_bounds__(256) out_kernel(float* __restrict__ out) {
    __shared__ float tile[64][65];
    __shared__ float ss[OUTC], tt[OUTC];
    int tid = threadIdx.x;
    if (tid < OUTC) { ss[tid] = g_s[tid]; tt[tid] = g_t[tid]; }
    __syncthreads();

    int p0 = blockIdx.x * 64;
    int b = p0 >> 12;
    int n0 = p0 & (NN - 1);

#pragma unroll
    for (int j = 0; j < 16; j++) {
        int i = tid + j * 256;
        int nn = i >> 6, o = i & 63;
        size_t base = (size_t)(p0 + nn) * OUTC + o;
        float s = ss[o];
        float z = (s >= 0.f) ? g_mx[base] : g_mn[base];
        float y = fmaf(s, z, tt[o]);
        y = (y >= 0.f) ? y : 0.2f * y;
        tile[o][nn] = y;
    }
    __syncthreads();
#pragma unroll
    for (int j = 0; j < 16; j++) {
        int i = tid + j * 256;
        int o = i >> 6, nn = i & 63;
        out[((size_t)(b * OUTC + o)) * NN + n0 + nn] = tile[o][nn];
    }
}

// ===================== launch =====================
extern "C" void kernel_launch(void* const* d_in, const int* in_sizes, int n_in,
                              void* d_out, int out_size) {
    const float* x     = (const float*)d_in[0];
    const float* W     = (const float*)d_in[1];
    const float* gamma = (const float*)d_in[2];
    const float* beta  = (const float*)d_in[3];
    float* out = (float*)d_out;

    cudaFuncSetAttribute(knn_gemm_kernel, cudaFuncAttributeMaxDynamicSharedMemorySize, SM_TOTAL);

    prep_kernel<<<(BB * NN) / 128, 128>>>(x);
    knn_gemm_kernel<<<dim3(NN / TM, BB), 256, SM_TOTAL>>>();
    select_rerank_kernel<<<BB * NN, 128>>>();
    gemm_uv_kernel<<<dim3(NN / 128, 8, BB), 128>>>(x, W);
    edge_kernel<<<(BB * NN) / 64, 256>>>();
    stats_kernel<<<1, OUTC>>>(gamma, beta);
    out_kernel<<<(BB * NN) / 64, 256>>>(out);
}